// round 17
// baseline (speedup 1.0000x reference)
#include <cuda_runtime.h>
#include <math.h>
#include <stdint.h>

#define Nn 4096
#define Lt 256
#define TLt 128
#define MUc 0.001f
#define Ac 0.999f          /* 1-mu */
#define NM1 4095.0f
#define INV_NM1 (1.0f/4095.0f)
#define EPSF 2.2204460492503131e-16f
#define NNsz ((size_t)Nn*(size_t)Nn)

typedef unsigned long long ull;

// ---- scratch (device globals; no allocations allowed) ----
__device__ __align__(16) uint32_t g_pk[Lt * 128];  // h packed to bits
__device__ float g_rho[Lt];
__device__ float g_cnt[Lt];              // per-row popcount
__device__ float g_inv[Nn];              // 1 / colsum of clip(a)*clip(b)
__device__ float g_aT[NNsz];             // alpha transposed
__device__ float g_bT[NNsz];             // beta transposed

// ---- packed f32x2 helpers ----
__device__ __forceinline__ ull pk2(float lo, float hi) {
    ull r; asm("mov.b64 %0,{%1,%2};" : "=l"(r) : "f"(lo), "f"(hi)); return r;
}
__device__ __forceinline__ void up2(ull v, float& lo, float& hi) {
    asm("mov.b64 {%0,%1},%2;" : "=f"(lo), "=f"(hi) : "l"(v));
}
__device__ __forceinline__ ull ffma2(ull a, ull b, ull c) {
    ull d; asm("fma.rn.f32x2 %0,%1,%2,%3;" : "=l"(d) : "l"(a), "l"(b), "l"(c)); return d;
}
__device__ __forceinline__ ull fmul2(ull a, ull b) {
    ull d; asm("mul.rn.f32x2 %0,%1,%2;" : "=l"(d) : "l"(a), "l"(b)); return d;
}
__device__ __forceinline__ ull fadd2(ull a, ull b) {
    ull d; asm("add.rn.f32x2 %0,%1,%2;" : "=l"(d) : "l"(a), "l"(b)); return d;
}
__device__ __forceinline__ float frcp_fast(float x) {
    float r; asm("rcp.approx.f32 %0,%1;" : "=f"(r) : "f"(x)); return r;
}

// rho[l] = -expm1(-n_e * m[l]),  n_e = 4*10000/4096 = 9.765625
__global__ void k_rho(float* __restrict__ rho, const float* __restrict__ m) {
    int t = threadIdx.x;
    if (t < Lt) rho[t] = -expm1f(-9.765625f * m[t]);
}

// pack h rows into bitmasks + per-row popcount
__global__ void k_pack(const int* __restrict__ h, uint32_t* __restrict__ pk,
                       float* __restrict__ cnt) {
    __shared__ int wsum[4];
    const int l = blockIdx.x;
    const int w = threadIdx.x;           // 0..127
    const int* row = h + (size_t)l * Nn + w * 32;
    uint32_t v = 0;
#pragma unroll
    for (int b = 0; b < 32; ++b) v |= ((uint32_t)(row[b] & 1)) << b;
    pk[l * 128 + w] = v;
    int c = __popc(v);
#pragma unroll
    for (int off = 16; off; off >>= 1) c += __shfl_xor_sync(0xFFFFFFFFu, c, off);
    if ((w & 31) == 0) wsum[w >> 5] = c;
    __syncthreads();
    if (w == 0) cnt[l] = (float)(wsum[0] + wsum[1] + wsum[2] + wsum[3]);
}

// ---- warp value-split butterfly: 4 partials -> per-warp totals, 6 SHFL.
// z at lanes (lane&7)==0 holds total for c = lane>>3.
__device__ __forceinline__ float warpSplit4(float s0, float s1, float s2, float s3,
                                            int lane) {
    const bool hi16 = (lane & 16) != 0, hi8 = (lane & 8) != 0;
    float tA = __shfl_xor_sync(0xFFFFFFFFu, hi16 ? s0 : s2, 16);
    float tB = __shfl_xor_sync(0xFFFFFFFFu, hi16 ? s1 : s3, 16);
    const float x = hi16 ? (s2 + tA) : (s0 + tA);
    const float y = hi16 ? (s3 + tB) : (s1 + tB);
    float tC = __shfl_xor_sync(0xFFFFFFFFu, hi8 ? x : y, 8);
    float z = (hi8 ? y : x) + tC;
    z += __shfl_xor_sync(0xFFFFFFFFu, z, 4);
    z += __shfl_xor_sync(0xFFFFFFFFu, z, 2);
    z += __shfl_xor_sync(0xFFFFFFFFu, z, 1);
    return z;
}

// ---- bwd-style one-barrier block sum of 4 partials (unchanged from R16) ----
__device__ __forceinline__ float4 blockSum4v2(float s0, float s1, float s2, float s3,
                                              float* sbuf, int t, int par) {
    const int lane = t & 31, w = t >> 5;
    float z = warpSplit4(s0, s1, s2, s3, lane);
    float* buf = sbuf + (par << 6);
    if ((lane & 7) == 0) buf[(w << 2) + (lane >> 3)] = z;
    __syncthreads();
    float v = buf[lane] + buf[lane + 32];
    v += __shfl_xor_sync(0xFFFFFFFFu, v, 4);
    v += __shfl_xor_sync(0xFFFFFFFFu, v, 8);
    v += __shfl_xor_sync(0xFFFFFFFFu, v, 16);
    float4 r;
    r.x = __shfl_sync(0xFFFFFFFFu, v, 0, 4);
    r.y = __shfl_sync(0xFFFFFFFFu, v, 1, 4);
    r.z = __shfl_sync(0xFFFFFFFFu, v, 2, 4);
    r.w = __shfl_sync(0xFFFFFFFFu, v, 3, 4);
    return r;
}

// ---- fwd fused 8-value reduction: push (S,Q) with ONE barrier ----
// sbuf layout: parity p occupies floats [p*128, p*128+128): S at +0, Q at +64.
__device__ __forceinline__ void push8(float s0, float s1, float s2, float s3,
                                      float q0, float q1, float q2, float q3,
                                      float* sbuf, int t, int par) {
    const int lane = t & 31, w = t >> 5;
    float zs = warpSplit4(s0, s1, s2, s3, lane);
    float zq = warpSplit4(q0, q1, q2, q3, lane);
    float* buf = sbuf + (par << 7);
    if ((lane & 7) == 0) {
        const int idx = (w << 2) + (lane >> 3);
        buf[idx] = zs;
        buf[64 + idx] = zq;
    }
    __syncthreads();
}
// light pull: S totals only (4 scalars)
__device__ __forceinline__ void pullS(const float* sbuf, int t, int par,
                                      float& S0, float& S1, float& S2, float& S3) {
    const int lane = t & 31;
    const float* buf = sbuf + (par << 7);
    float v = buf[lane] + buf[lane + 32];
    v += __shfl_xor_sync(0xFFFFFFFFu, v, 4);
    v += __shfl_xor_sync(0xFFFFFFFFu, v, 8);
    v += __shfl_xor_sync(0xFFFFFFFFu, v, 16);
    S0 = __shfl_sync(0xFFFFFFFFu, v, 0, 4);
    S1 = __shfl_sync(0xFFFFFFFFu, v, 1, 4);
    S2 = __shfl_sync(0xFFFFFFFFu, v, 2, 4);
    S3 = __shfl_sync(0xFFFFFFFFu, v, 3, 4);
}
// full pull: S and Q as packed pairs
__device__ __forceinline__ void pull8(const float* sbuf, int t, int par,
                                      ull& Sp0, ull& Sp1, ull& Qp0, ull& Qp1) {
    const int lane = t & 31;
    const float* buf = sbuf + (par << 7);
    float vs = buf[lane] + buf[lane + 32];
    float vq = buf[64 + lane] + buf[96 + lane];
    vs += __shfl_xor_sync(0xFFFFFFFFu, vs, 4);
    vs += __shfl_xor_sync(0xFFFFFFFFu, vs, 8);
    vs += __shfl_xor_sync(0xFFFFFFFFu, vs, 16);
    vq += __shfl_xor_sync(0xFFFFFFFFu, vq, 4);
    vq += __shfl_xor_sync(0xFFFFFFFFu, vq, 8);
    vq += __shfl_xor_sync(0xFFFFFFFFu, vq, 16);
    Sp0 = pk2(__shfl_sync(0xFFFFFFFFu, vs, 0, 4), __shfl_sync(0xFFFFFFFFu, vs, 1, 4));
    Sp1 = pk2(__shfl_sync(0xFFFFFFFFu, vs, 2, 4), __shfl_sync(0xFFFFFFFFu, vs, 3, 4));
    Qp0 = pk2(__shfl_sync(0xFFFFFFFFu, vq, 0, 4), __shfl_sync(0xFFFFFFFFu, vq, 1, 4));
    Qp1 = pk2(__shfl_sync(0xFFFFFFFFu, vq, 2, 4), __shfl_sync(0xFFFFFFFFu, vq, 3, 4));
}

// diag fix (bwd + fwd plain): subtract diag values from sums AND zero lanes.
__device__ __forceinline__ void diag_fix_fwd(ull& a0, ull& a1, ull& b2, ull& b3,
                                             ull& s0, ull& s1) {
    float lo, hi, sl, sh;
    up2(s0, sl, sh);
    up2(a0, lo, hi); sl -= lo; a0 = pk2(0.f, hi);
    up2(a1, lo, hi); sh -= hi; a1 = pk2(lo, 0.f);
    s0 = pk2(sl, sh);
    up2(s1, sl, sh);
    up2(b2, lo, hi); sl -= lo; b2 = pk2(0.f, hi);
    up2(b3, lo, hi); sh -= hi; b3 = pk2(lo, 0.f);
    s1 = pk2(sl, sh);
}
// fwd even-step fix: also conditionally subtract from Q per hn bits.
__device__ __forceinline__ void diag_fix_fwd_q(ull& a0, ull& a1, ull& b2, ull& b3,
                                               ull& s0, ull& s1, ull& q0, ull& q1,
                                               uint32_t hnb) {
    float lo, hi, sl, sh, ql, qh;
    up2(s0, sl, sh); up2(q0, ql, qh);
    up2(a0, lo, hi); sl -= lo; if (hnb & 1u) ql -= lo; a0 = pk2(0.f, hi);
    up2(a1, lo, hi); sh -= hi; if (hnb & 2u) qh -= hi; a1 = pk2(lo, 0.f);
    s0 = pk2(sl, sh); q0 = pk2(ql, qh);
    up2(s1, sl, sh); up2(q1, ql, qh);
    up2(b2, lo, hi); sl -= lo; if (hnb & 4u) ql -= lo; b2 = pk2(0.f, hi);
    up2(b3, lo, hi); sh -= hi; if (hnb & 8u) qh -= hi; b3 = pk2(lo, 0.f);
    s1 = pk2(sl, sh); q1 = pk2(ql, qh);
}
__device__ __forceinline__ void diag_zero(ull& a0, ull& a1, ull& b2, ull& b3) {
    a0 &= 0xFFFFFFFF00000000ull;
    a1 &= 0x00000000FFFFFFFFull;
    b2 &= 0xFFFFFFFF00000000ull;
    b3 &= 0x00000000FFFFFFFFull;
}

// transposed final store: thread owns rows r0..r0+7, cols j0..j0+3
__device__ __forceinline__ void store_T(float* __restrict__ xT, const ull st[8][2],
                                        int j0, int r0) {
#pragma unroll
    for (int c = 0; c < 4; ++c) {
        float v[8];
#pragma unroll
        for (int r = 0; r < 8; ++r) {
            float lo, hi; up2(st[r][c >> 1], lo, hi);
            v[r] = (c & 1) ? hi : lo;
        }
        float* base = xT + (size_t)(j0 + c) * Nn + r0;
        *(float4*)base       = make_float4(v[0], v[1], v[2], v[3]);
        *(float4*)(base + 4) = make_float4(v[4], v[5], v[6], v[7]);
    }
}

// Precompute packed emission table: sE[s*4+{0..3}] = E0p0,E1p0,E0p1,E1p1.
__device__ __forceinline__ void precompE(ull* sE, int nSteps, int rowBase,
                                         int rowStride, int jWord, int jSh, int t) {
    for (int s = t; s < nSteps; s += 512) {
        const int lr = rowBase + s * rowStride;
        const uint32_t hj = (__ldg(g_pk + lr * 128 + jWord) >> jSh) & 0xFu;
        const float e0a = (hj & 1u) ? MUc : Ac, e1a = (hj & 1u) ? Ac : MUc;
        const float e0b = (hj & 2u) ? MUc : Ac, e1b = (hj & 2u) ? Ac : MUc;
        const float e0c = (hj & 4u) ? MUc : Ac, e1c = (hj & 4u) ? Ac : MUc;
        const float e0d = (hj & 8u) ? MUc : Ac, e1d = (hj & 8u) ? Ac : MUc;
        ull* e = sE + (s << 2);
        e[0] = pk2(e0a, e0b); e[1] = pk2(e1a, e1b);
        e[2] = pk2(e0c, e0d); e[3] = pk2(e1c, e1d);
    }
}

// ---------------- forward body: 2 steps per barrier ----------------
// even steps reduce (S, Q); odd steps have NO reduction; S of odd steps is
// reconstructed analytically: U = e0*(S-Q)+e1*Q, Theta = e1*c1+e0*(N-c1)-Ac,
// S_odd = wp*U + cst*Theta.  (algebra validated in a prior passing round)
__device__ __forceinline__ void fwd_body(float* __restrict__ aT, int blk,
                                         float* sbuf, float* srho, float* scnt,
                                         ull* sE) {
    const int t = threadIdx.x;
    const int j0 = blk << 2;
    const int r0 = t << 3;
    if (t < Lt) { srho[t] = g_rho[t]; scnt[t] = g_cnt[t]; }

    const int wWord = r0 >> 5, wSh = r0 & 31;
    const int jWord = j0 >> 5, jSh = j0 & 31;
    const bool isDiagT = (t == (j0 >> 3));
    const bool diagHi = (j0 & 7) != 0;

    precompE(sE, TLt + 1, 0, 1, jWord, jSh, t);

    ull st[8][2];
#pragma unroll
    for (int r = 0; r < 8; ++r) { st[r][0] = 0ull; st[r][1] = 0ull; }
    __syncthreads();

    ull wp0 = 0ull, wp1 = 0ull, cstp = pk2(INV_NM1, INV_NM1);

    // ---- step 0 (even: Q-accumulating loop + push) ----
    {
        const uint32_t hb = __ldg(g_pk + wWord) >> wSh;
        const uint32_t hn = __ldg(g_pk + 128 + wWord) >> wSh;
        const ull E0p0 = sE[0], E1p0 = sE[1], E0p1 = sE[2], E1p1 = sE[3];
        ull sm0 = 0ull, sm1 = 0ull, q0 = 0ull, q1 = 0ull;
#pragma unroll
        for (int r = 0; r < 8; ++r) {
            const bool hi = (hb >> r) & 1u;
            const bool qn = (hn >> r) & 1u;
            const ull o0 = fmul2(ffma2(st[r][0], wp0, cstp), hi ? E1p0 : E0p0);
            const ull o1 = fmul2(ffma2(st[r][1], wp1, cstp), hi ? E1p1 : E0p1);
            st[r][0] = o0; st[r][1] = o1;
            sm0 = fadd2(sm0, o0); sm1 = fadd2(sm1, o1);
            q0 = fadd2(q0, qn ? o0 : 0ull); q1 = fadd2(q1, qn ? o1 : 0ull);
        }
        if (isDiagT) {
            if (diagHi) diag_fix_fwd_q(st[4][0], st[5][0], st[6][1], st[7][1],
                                       sm0, sm1, q0, q1, hn >> 4);
            else        diag_fix_fwd_q(st[0][0], st[1][0], st[2][1], st[3][1],
                                       sm0, sm1, q0, q1, hn);
        }
        float a0, a1, a2, a3, b0, b1, b2, b3;
        up2(sm0, a0, a1); up2(sm1, a2, a3);
        up2(q0, b0, b1);  up2(q1, b2, b3);
        push8(a0, a1, a2, a3, b0, b1, b2, b3, sbuf, t, 0);
    }

    for (int m = 1; m <= 64; ++m) {
        const int so = 2 * m - 1, se = 2 * m;
        // ======== odd step so: pulled S, NO sums, NO reduction ========
        {
            float S0, S1, S2, S3;
            pullS(sbuf, t, (m - 1) & 1, S0, S1, S2, S3);
            const float rr = srho[so - 1];
            const float wv = 1.0f - rr;
            wp0 = pk2(wv * frcp_fast(S0), wv * frcp_fast(S1));
            wp1 = pk2(wv * frcp_fast(S2), wv * frcp_fast(S3));
            cstp = pk2(rr * INV_NM1, rr * INV_NM1);
            const uint32_t hb = __ldg(g_pk + so * 128 + wWord) >> wSh;
            const ull* Ep = sE + (so << 2);
            const ull E0p0 = Ep[0], E1p0 = Ep[1], E0p1 = Ep[2], E1p1 = Ep[3];
#pragma unroll
            for (int r = 0; r < 8; ++r) {
                const bool hi = (hb >> r) & 1u;
                st[r][0] = fmul2(ffma2(st[r][0], wp0, cstp), hi ? E1p0 : E0p0);
                st[r][1] = fmul2(ffma2(st[r][1], wp1, cstp), hi ? E1p1 : E0p1);
            }
            if (isDiagT) {
                if (diagHi) diag_zero(st[4][0], st[5][0], st[6][1], st[7][1]);
                else        diag_zero(st[0][0], st[1][0], st[2][1], st[3][1]);
            }
        }
        // ======== even step se: analytic S_{so}, loop with sums, push ========
        {
            ull Sp0, Sp1, Qp0, Qp1;
            pull8(sbuf, t, (m - 1) & 1, Sp0, Sp1, Qp0, Qp1);  // sums of step se-2
            const ull* Em = sE + (so << 2);
            const ull E0m0 = Em[0], E1m0 = Em[1], E0m1 = Em[2], E1m1 = Em[3];
            const float c1 = scnt[so];
            const ull c1p = pk2(c1, c1), nc1p = pk2(4096.0f - c1, 4096.0f - c1);
            const ull negOne2 = pk2(-1.0f, -1.0f), negAc2 = pk2(-Ac, -Ac);
            const ull SmQ0 = ffma2(Qp0, negOne2, Sp0);
            const ull SmQ1 = ffma2(Qp1, negOne2, Sp1);
            const ull U0 = fadd2(fmul2(E0m0, SmQ0), fmul2(E1m0, Qp0));
            const ull U1 = fadd2(fmul2(E0m1, SmQ1), fmul2(E1m1, Qp1));
            ull Th0 = fadd2(ffma2(E1m0, c1p, fmul2(E0m0, nc1p)), negAc2);
            ull Th1 = fadd2(ffma2(E1m1, c1p, fmul2(E0m1, nc1p)), negAc2);
            const ull S10 = ffma2(wp0, U0, fmul2(cstp, Th0));
            const ull S11 = ffma2(wp1, U1, fmul2(cstp, Th1));
            float sa, sb, sc, sd;
            up2(S10, sa, sb); up2(S11, sc, sd);
            const float rr2 = srho[se - 1];
            const float wv2 = 1.0f - rr2;
            wp0 = pk2(wv2 * frcp_fast(sa), wv2 * frcp_fast(sb));
            wp1 = pk2(wv2 * frcp_fast(sc), wv2 * frcp_fast(sd));
            cstp = pk2(rr2 * INV_NM1, rr2 * INV_NM1);

            const uint32_t hb = __ldg(g_pk + se * 128 + wWord) >> wSh;
            const ull* Ep = sE + (se << 2);
            const ull E0p0 = Ep[0], E1p0 = Ep[1], E0p1 = Ep[2], E1p1 = Ep[3];
            if (m < 64) {
                const uint32_t hn = __ldg(g_pk + (se + 1) * 128 + wWord) >> wSh;
                ull sm0 = 0ull, sm1 = 0ull, q0 = 0ull, q1 = 0ull;
#pragma unroll
                for (int r = 0; r < 8; ++r) {
                    const bool hi = (hb >> r) & 1u;
                    const bool qn = (hn >> r) & 1u;
                    const ull o0 = fmul2(ffma2(st[r][0], wp0, cstp), hi ? E1p0 : E0p0);
                    const ull o1 = fmul2(ffma2(st[r][1], wp1, cstp), hi ? E1p1 : E0p1);
                    st[r][0] = o0; st[r][1] = o1;
                    sm0 = fadd2(sm0, o0); sm1 = fadd2(sm1, o1);
                    q0 = fadd2(q0, qn ? o0 : 0ull); q1 = fadd2(q1, qn ? o1 : 0ull);
                }
                if (isDiagT) {
                    if (diagHi) diag_fix_fwd_q(st[4][0], st[5][0], st[6][1], st[7][1],
                                               sm0, sm1, q0, q1, hn >> 4);
                    else        diag_fix_fwd_q(st[0][0], st[1][0], st[2][1], st[3][1],
                                               sm0, sm1, q0, q1, hn);
                }
                float a0, a1, a2, a3, b0, b1, b2, b3;
                up2(sm0, a0, a1); up2(sm1, a2, a3);
                up2(q0, b0, b1);  up2(q1, b2, b3);
                push8(a0, a1, a2, a3, b0, b1, b2, b3, sbuf, t, m & 1);
            } else {
                // final step 128: plain update, no reduction
#pragma unroll
                for (int r = 0; r < 8; ++r) {
                    const bool hi = (hb >> r) & 1u;
                    st[r][0] = fmul2(ffma2(st[r][0], wp0, cstp), hi ? E1p0 : E0p0);
                    st[r][1] = fmul2(ffma2(st[r][1], wp1, cstp), hi ? E1p1 : E0p1);
                }
                if (isDiagT) {
                    if (diagHi) diag_zero(st[4][0], st[5][0], st[6][1], st[7][1]);
                    else        diag_zero(st[0][0], st[1][0], st[2][1], st[3][1]);
                }
            }
        }
    }
    store_T(aT, st, j0, r0);
}

// ---------------- backward body: unchanged from best (R16) --------------------
__device__ __forceinline__ void bwd_body(float* __restrict__ bT, int blk,
                                         float* sbuf, float* srho, ull* sE) {
    const int t = threadIdx.x;
    const int j0 = blk << 2;
    const int r0 = t << 3;
    if (t < Lt) srho[t] = g_rho[t];

    const int wWord = r0 >> 5, wSh = r0 & 31;
    const int jWord = j0 >> 5, jSh = j0 & 31;
    const bool isDiagT = (t == (j0 >> 3));
    const bool diagHi = (j0 & 7) != 0;
    const int NB = Lt - 1 - TLt;  // 127

    precompE(sE, NB, Lt - 1, -1, jWord, jSh, t);

    ull st[8][2];
    const ull one2 = pk2(1.0f, 1.0f);
#pragma unroll
    for (int r = 0; r < 8; ++r) { st[r][0] = one2; st[r][1] = one2; }
    __syncthreads();

    ull kp0 = 0ull, kp1 = 0ull;
    ull rp = one2;
    for (int k = 0; k < NB; ++k) {
        const uint32_t hb = __ldg(g_pk + (Lt - 1 - k) * 128 + wWord) >> wSh;
        const ull* Ep = sE + (k << 2);
        const ull E0p0 = Ep[0], E1p0 = Ep[1], E0p1 = Ep[2], E1p1 = Ep[3];

        ull sm0a = 0ull, sm0b = 0ull, sm1a = 0ull, sm1b = 0ull;
#pragma unroll
        for (int r = 0; r < 8; ++r) {
            const bool hi = (hb >> r) & 1u;
            const ull u0 = fmul2(hi ? E1p0 : E0p0, ffma2(st[r][0], kp0, rp));
            const ull u1 = fmul2(hi ? E1p1 : E0p1, ffma2(st[r][1], kp1, rp));
            st[r][0] = u0; st[r][1] = u1;
            if (r & 1) { sm0b = fadd2(sm0b, u0); sm1b = fadd2(sm1b, u1); }
            else       { sm0a = fadd2(sm0a, u0); sm1a = fadd2(sm1a, u1); }
        }
        ull sm0 = fadd2(sm0a, sm0b), sm1 = fadd2(sm1a, sm1b);
        if (isDiagT) {
            if (diagHi) diag_fix_fwd(st[4][0], st[5][0], st[6][1], st[7][1], sm0, sm1);
            else        diag_fix_fwd(st[0][0], st[1][0], st[2][1], st[3][1], sm0, sm1);
        }
        float a0, a1, a2, a3;
        up2(sm0, a0, a1); up2(sm1, a2, a3);
        const float4 tot = blockSum4v2(a0, a1, a2, a3, sbuf, t, k & 1);

        const float rr = srho[Lt - 2 - k];
        const float ks = (1.0f - rr) * NM1;
        kp0 = pk2(ks * frcp_fast(tot.x), ks * frcp_fast(tot.y));
        kp1 = pk2(ks * frcp_fast(tot.z), ks * frcp_fast(tot.w));
        rp = pk2(rr, rr);
    }
#pragma unroll
    for (int r = 0; r < 8; ++r) {
        st[r][0] = ffma2(st[r][0], kp0, rp);
        st[r][1] = ffma2(st[r][1], kp1, rp);
    }
    if (isDiagT) {
        if (diagHi) diag_zero(st[4][0], st[5][0], st[6][1], st[7][1]);
        else        diag_zero(st[0][0], st[1][0], st[2][1], st[3][1]);
    }
    store_T(bT, st, j0, r0);
}

// merged: blocks [0,1024) run forward, [1024,2048) run backward
__global__ void __launch_bounds__(512, 2) k_main(float* __restrict__ aT,
                                                 float* __restrict__ bT) {
    __shared__ __align__(16) float sbuf[256];   // fwd: 2 parities x 128; bwd uses 2x64
    __shared__ float srho[Lt];
    __shared__ float scnt[Lt];
    __shared__ __align__(16) ull sE[(TLt + 1) * 4];
    if (blockIdx.x < 1024) fwd_body(aT, blockIdx.x, sbuf, srho, scnt, sE);
    else                   bwd_body(bT, blockIdx.x - 1024, sbuf, srho, sE);
}

// column sums of clip(a)*clip(b) -> inv[j]; block owns 4 rows of a^T/b^T
__global__ void __launch_bounds__(512, 2) k_colsum(const float* __restrict__ aT,
                                                   const float* __restrict__ bT,
                                                   float* __restrict__ inv) {
    __shared__ float4 swarp[16];
    const int t = threadIdx.x;
    const int j0 = blockIdx.x << 2;
    float s[4] = {0.f, 0.f, 0.f, 0.f};
#pragma unroll
    for (int jj = 0; jj < 4; ++jj) {
        const float4* a4 = (const float4*)aT + (size_t)(j0 + jj) * 1024;
        const float4* b4 = (const float4*)bT + (size_t)(j0 + jj) * 1024;
#pragma unroll
        for (int k2 = 0; k2 < 2; ++k2) {
            const int idx = t + (k2 << 9);
            const float4 av = __ldg(a4 + idx);
            const float4 bv = __ldg(b4 + idx);
            s[jj] += __saturatef(av.x) * __saturatef(bv.x)
                   + __saturatef(av.y) * __saturatef(bv.y)
                   + __saturatef(av.z) * __saturatef(bv.z)
                   + __saturatef(av.w) * __saturatef(bv.w);
        }
    }
#pragma unroll
    for (int off = 16; off; off >>= 1) {
        s[0] += __shfl_xor_sync(0xFFFFFFFFu, s[0], off);
        s[1] += __shfl_xor_sync(0xFFFFFFFFu, s[1], off);
        s[2] += __shfl_xor_sync(0xFFFFFFFFu, s[2], off);
        s[3] += __shfl_xor_sync(0xFFFFFFFFu, s[3], off);
    }
    if ((t & 31) == 0) swarp[t >> 5] = make_float4(s[0], s[1], s[2], s[3]);
    __syncthreads();
    if (t == 0) {
        float4 v = swarp[0];
#pragma unroll
        for (int w = 1; w < 16; ++w) {
            float4 q = swarp[w];
            v.x += q.x; v.y += q.y; v.z += q.z; v.w += q.w;
        }
        inv[j0] = 1.0f / v.x; inv[j0 + 1] = 1.0f / v.y;
        inv[j0 + 2] = 1.0f / v.z; inv[j0 + 3] = 1.0f / v.w;
    }
}

// fused epilogue: p + d + alpha/beta std-layout, all from aT/bT tiles.
__global__ void k_out(const float* __restrict__ aT, const float* __restrict__ bT,
                      const float* __restrict__ inv,
                      float* __restrict__ p, float* __restrict__ d,
                      float* __restrict__ aStd, float* __restrict__ bStd) {
    const int bi = blockIdx.y, bj = blockIdx.x;
    if (bj < bi) return;
    __shared__ float PA[32][33], PB[32][33];
    __shared__ float AA[32][33], BA[32][33];
    __shared__ float AB[32][33], BB[32][33];
    const int tx = threadIdx.x & 31;
    const int ty0 = threadIdx.x >> 5;
    const bool diagBlk = (bi == bj);
#pragma unroll
    for (int k2 = 0; k2 < 4; ++k2) {
        const int y = ty0 + (k2 << 3);
        const int ja = (bi << 5) + y;
        const size_t offA = (size_t)ja * Nn + (bj << 5) + tx;
        const float av = __ldg(aT + offA);
        const float bv = __ldg(bT + offA);
        AA[y][tx] = av; BA[y][tx] = bv;
        PA[y][tx] = __saturatef(av) * __saturatef(bv) * __ldg(inv + ja);
        if (!diagBlk) {
            const int jb = (bj << 5) + y;
            const size_t offB = (size_t)jb * Nn + (bi << 5) + tx;
            const float av2 = __ldg(aT + offB);
            const float bv2 = __ldg(bT + offB);
            AB[y][tx] = av2; BB[y][tx] = bv2;
            PB[y][tx] = __saturatef(av2) * __saturatef(bv2) * __ldg(inv + jb);
        }
    }
    __syncthreads();
#pragma unroll
    for (int k2 = 0; k2 < 4; ++k2) {
        const int y = ty0 + (k2 << 3);
        const size_t o1 = (size_t)((bj << 5) + y) * Nn + (bi << 5) + tx;
        p[o1] = PA[tx][y];
        if (aStd) { aStd[o1] = AA[tx][y]; bStd[o1] = BA[tx][y]; }
        if (!diagBlk) {
            const size_t o2 = (size_t)((bi << 5) + y) * Nn + (bj << 5) + tx;
            p[o2] = PB[tx][y];
            if (aStd) { aStd[o2] = AB[tx][y]; bStd[o2] = BB[tx][y]; }
        }
    }
    if (d == nullptr) return;
    __syncthreads();
#pragma unroll
    for (int k2 = 0; k2 < 4; ++k2) {
        const int y = ty0 + (k2 << 3);
        PA[y][tx] = __logf(fmaxf(PA[y][tx], EPSF));
        if (!diagBlk) PB[y][tx] = __logf(fmaxf(PB[y][tx], EPSF));
    }
    __syncthreads();
    float (*LB)[33] = diagBlk ? PA : PB;
#pragma unroll
    for (int k2 = 0; k2 < 4; ++k2) {
        const int y = ty0 + (k2 << 3);
        float dv = -0.5f * (LB[tx][y] + PA[y][tx]);
        if (diagBlk && y == tx) dv = 0.0f;
        d[(size_t)((bi << 5) + y) * Nn + (bj << 5) + tx] = dv;
        if (!diagBlk)
            d[(size_t)((bj << 5) + y) * Nn + (bi << 5) + tx]
                = -0.5f * (PA[tx][y] + LB[y][tx]);
    }
}

extern "C" void kernel_launch(void* const* d_in, const int* in_sizes, int n_in,
                              void* d_out, int out_size) {
    const int* h = (const int*)d_in[0];
    const float* m = (const float*)d_in[1];
    float* out = (float*)d_out;

    void* sym;
    uint32_t* pk; float *rho, *cnt, *aT, *bT, *inv;
    cudaGetSymbolAddress(&sym, g_pk);  pk  = (uint32_t*)sym;
    cudaGetSymbolAddress(&sym, g_rho); rho = (float*)sym;
    cudaGetSymbolAddress(&sym, g_cnt); cnt = (float*)sym;
    cudaGetSymbolAddress(&sym, g_aT);  aT  = (float*)sym;
    cudaGetSymbolAddress(&sym, g_bT);  bT  = (float*)sym;
    cudaGetSymbolAddress(&sym, g_inv); inv = (float*)sym;

    float *pOut, *dOut, *alphaStd, *betaStd;
    size_t osz = (size_t)out_size;
    if (osz >= 4 * NNsz) {
        pOut = out; dOut = out + NNsz;
        alphaStd = out + 2 * NNsz; betaStd = out + 3 * NNsz;
    } else if (osz >= 2 * NNsz) {
        pOut = out; dOut = out + NNsz; alphaStd = nullptr; betaStd = nullptr;
    } else {
        pOut = out; dOut = nullptr; alphaStd = nullptr; betaStd = nullptr;
    }

    k_rho<<<1, 256>>>(rho, m);
    k_pack<<<Lt, 128>>>(h, pk, cnt);
    k_main<<<2048, 512>>>(aT, bT);
    k_colsum<<<Nn / 4, 512>>>(aT, bT, inv);
    dim3 g2(Nn / 32, Nn / 32);
    k_out<<<g2, 256>>>(aT, bT, inv, pOut, dOut, alphaStd, betaStd);
}